// round 14
// baseline (speedup 1.0000x reference)
#include <cuda_runtime.h>
#include <cuda_bf16.h>
#include <math.h>
#include <stdint.h>

#define N_PIX 9216
#define C_DIM 64
#define NT_HALF 72   // 144 key-tiles of 64, split-K across 2 CTAs -> 72 each

// Does this compilation pass have the arch-specific tcgen05 ISA?
#if defined(__CUDA_ARCH_FEAT_SM103_ALL) || defined(__CUDA_ARCH_FEAT_SM100_ALL) || \
    (defined(__CUDA_ARCH_SPECIFIC__) && defined(__CUDA_ARCH__) && (__CUDA_ARCH__ == 1030))
#define TC_OK 1
#else
#define TC_OK 0
#endif

// ------------------------------ device scratch ------------------------------
__device__ float g_y[C_DIM * N_PIX];                 // dilated conv out, [c][pix]
__device__ float g_v[C_DIM * N_PIX];                 // 1x1 conv out ([m][c] flat view)
__device__ __align__(16) __nv_bfloat16 g_qs[N_PIX * 192]; // [n][s*64+c]
__device__ __align__(16) __nv_bfloat16 g_ks[N_PIX * 192]; // [m][s*64+c]
__device__ __align__(16) __nv_bfloat16 g_vs[64 * 2 * N_PIX]; // [(c*2+s)][m]
__device__ float g_qn[N_PIX];                        // ||q_n||
__device__ int   g_KmaxBits;                         // max_m ||k_m|| (float bits)
__device__ float g_O[2 * 64 * N_PIX];                // partial O: [(half*64+c)][n]
__device__ float g_l[2 * N_PIX];                     // partial l

// ---------------------------------------------------------------------------
// Dilated 3x3 conv
// ---------------------------------------------------------------------------
__global__ void __launch_bounds__(512, 1)
dconv_kernel(const float* __restrict__ x, const float* __restrict__ dW,
             const float* __restrict__ db) {
    extern __shared__ float xs[];
    const int ROWW = 100;
    int h = blockIdx.x, tid = threadIdx.x;
    for (int i = tid; i < 3 * 64 * ROWW; i += 512) xs[i] = 0.f;
    __syncthreads();
    for (int i = tid; i < 3 * 64 * 96; i += 512) {
        int r = i / (64 * 96), rem = i % (64 * 96);
        int ci = rem / 96, w = rem % 96;
        int hh = h + 2 * (r - 1);
        if (hh >= 0 && hh < 96)
            xs[(r * 64 + ci) * ROWW + w + 2] = x[ci * N_PIX + hh * 96 + w];
    }
    __syncthreads();
    int c = tid >> 3, w0 = (tid & 7) * 12;
    float acc[12];
    float b = __ldg(&db[c]);
#pragma unroll
    for (int k = 0; k < 12; k++) acc[k] = b;
    const float* wbase = &dW[c * 576];
    float wg[9];
#pragma unroll
    for (int t = 0; t < 9; t++) wg[t] = __ldg(&wbase[t]);
    for (int ci = 0; ci < 64; ci++) {
        float wgn[9];
        if (ci < 63) {
#pragma unroll
            for (int t = 0; t < 9; t++) wgn[t] = __ldg(&wbase[(ci + 1) * 9 + t]);
        }
#pragma unroll
        for (int r = 0; r < 3; r++) {
            const float* xp = &xs[(r * 64 + ci) * ROWW + w0];
#pragma unroll
            for (int kw = 0; kw < 3; kw++) {
                float w = wg[r * 3 + kw];
#pragma unroll
                for (int k = 0; k < 12; k++) acc[k] += xp[k + 2 * kw] * w;
            }
        }
#pragma unroll
        for (int t = 0; t < 9; t++) wg[t] = wgn[t];
    }
    float* yo = &g_y[c * N_PIX + h * 96 + w0];
#pragma unroll
    for (int k = 0; k < 12; k++) yo[k] = acc[k];
}

// ---------------------------------------------------------------------------
__global__ void conv1x1_kernel(const float* __restrict__ x,
                               const float* __restrict__ cW,
                               const float* __restrict__ cb) {
    __shared__ float ws[64 * 64];
    int tid = threadIdx.x;
    if (blockIdx.x == 0 && tid == 0) g_KmaxBits = 0;
    for (int i = tid; i < 4096; i += 128) ws[i] = cW[i];
    __syncthreads();
    int p = blockIdx.x * 128 + tid;
#pragma unroll 1
    for (int chunk = 0; chunk < 4; chunk++) {
        float acc[16];
#pragma unroll
        for (int j = 0; j < 16; j++) acc[j] = __ldg(&cb[chunk * 16 + j]);
        for (int ci = 0; ci < 64; ci++) {
            float xv = x[ci * N_PIX + p];
#pragma unroll
            for (int j = 0; j < 16; j++)
                acc[j] += xv * ws[(chunk * 16 + j) * 64 + ci];
        }
#pragma unroll
        for (int j = 0; j < 16; j++) g_v[(chunk * 16 + j) * N_PIX + p] = acc[j];
    }
}

// ---------------------------------------------------------------------------
// Split kernel: bf16 3-way splits of Q rows / K cols, 2-way split of V rows,
// plus ||q_n|| and global max ||k_m||.
// ---------------------------------------------------------------------------
__global__ void __launch_bounds__(256, 1) split_kernel() {
    __shared__ float yb[64 * 65];
    __shared__ __nv_bfloat16 ob[64 * 192];
    int tid = threadIdx.x, blk = blockIdx.x;
    int r = tid >> 2, p4 = tid & 3;

    // Q rows
    for (int i = tid; i < 4096; i += 256) yb[i] = g_y[blk * 4096 + i];
    __syncthreads();
    {
        float nrm = 0.f;
#pragma unroll
        for (int cc = 0; cc < 16; cc++) {
            int c = p4 * 16 + cc;
            float v = yb[r * 64 + c];
            nrm += v * v;
            __nv_bfloat16 b0 = __float2bfloat16(v);
            float r1 = v - __bfloat162float(b0);
            __nv_bfloat16 b1 = __float2bfloat16(r1);
            __nv_bfloat16 b2 = __float2bfloat16(r1 - __bfloat162float(b1));
            ob[r * 192 + c] = b0; ob[r * 192 + 64 + c] = b1; ob[r * 192 + 128 + c] = b2;
        }
        nrm += __shfl_xor_sync(0xffffffffu, nrm, 1);
        nrm += __shfl_xor_sync(0xffffffffu, nrm, 2);
        if (p4 == 0) g_qn[blk * 64 + r] = sqrtf(nrm);
    }
    __syncthreads();
    for (int i = tid; i < 1536; i += 256)
        reinterpret_cast<uint4*>(g_qs)[blk * 1536 + i] =
            reinterpret_cast<const uint4*>(ob)[i];
    __syncthreads();

    // K cols
    for (int i = tid; i < 4096; i += 256) {
        int c = i >> 6, ml = i & 63;
        yb[ml * 65 + c] = g_y[c * N_PIX + blk * 64 + ml];
    }
    __syncthreads();
    {
        float nrm = 0.f;
#pragma unroll
        for (int cc = 0; cc < 16; cc++) {
            int c = p4 * 16 + cc;
            float v = yb[r * 65 + c];
            nrm += v * v;
            __nv_bfloat16 b0 = __float2bfloat16(v);
            float r1 = v - __bfloat162float(b0);
            __nv_bfloat16 b1 = __float2bfloat16(r1);
            __nv_bfloat16 b2 = __float2bfloat16(r1 - __bfloat162float(b1));
            ob[r * 192 + c] = b0; ob[r * 192 + 64 + c] = b1; ob[r * 192 + 128 + c] = b2;
        }
        nrm += __shfl_xor_sync(0xffffffffu, nrm, 1);
        nrm += __shfl_xor_sync(0xffffffffu, nrm, 2);
        if (p4 == 0) atomicMax(&g_KmaxBits, __float_as_int(sqrtf(nrm)));
    }
    __syncthreads();
    for (int i = tid; i < 1536; i += 256)
        reinterpret_cast<uint4*>(g_ks)[blk * 1536 + i] =
            reinterpret_cast<const uint4*>(ob)[i];
    __syncthreads();

    // V rows, 2-way split, stored transposed [(c*2+s)][m]
    for (int i = tid; i < 4096; i += 256) yb[i] = g_v[blk * 4096 + i];
    __syncthreads();
#pragma unroll
    for (int cc = 0; cc < 16; cc++) {
        int c = p4 * 16 + cc;
        float v = yb[r * 64 + c];
        __nv_bfloat16 b0 = __float2bfloat16(v);
        __nv_bfloat16 b1 = __float2bfloat16(v - __bfloat162float(b0));
        ob[(c * 2 + 0) * 64 + r] = b0;
        ob[(c * 2 + 1) * 64 + r] = b1;
    }
    __syncthreads();
    for (int i = tid; i < 1024; i += 256)
        reinterpret_cast<uint4*>(g_vs)[(i >> 3) * 1152 + blk * 8 + (i & 7)] =
            reinterpret_cast<const uint4*>(ob)[i];
}

// ============================ tcgen05 path ===================================
#if TC_OK
__device__ __forceinline__ uint32_t smem_u32(const void* p) {
    uint32_t a;
    asm("{ .reg .u64 t; cvta.to.shared.u64 t, %1; cvt.u32.u64 %0, t; }"
        : "=r"(a) : "l"(p));
    return a;
}
__device__ __forceinline__ uint32_t elect_one() {
    uint32_t pred;
    asm volatile("{ .reg .pred p; elect.sync _|p, 0xFFFFFFFF; selp.b32 %0,1,0,p; }"
                 : "=r"(pred));
    return pred;
}
#define MBAR_INIT(a, c) \
    asm volatile("mbarrier.init.shared.b64 [%0], %1;" :: "r"(a), "r"(c) : "memory")
#define MBAR_WAIT(a, ph) do {                                                    \
    uint32_t _m = (a), _p = (uint32_t)(ph), _d;                                  \
    asm volatile("{ .reg .pred p; mbarrier.try_wait.parity.acquire.cta.shared::cta.b64 p, [%1], %2;" \
                 " selp.b32 %0,1,0,p; }" : "=r"(_d) : "r"(_m), "r"(_p) : "memory"); \
    if (!_d) asm volatile("{ .reg .pred P1; W%=:\n\t"                            \
                 "mbarrier.try_wait.parity.acquire.cta.shared::cta.b64 P1, [%0], %1, 0x989680;\n\t" \
                 "@P1 bra.uni D%=;\n\t bra.uni W%=;\n\t D%=: }"                  \
                 :: "r"(_m), "r"(_p) : "memory");                                \
} while (0)
#define TC_ALLOC(a, n)   asm volatile("tcgen05.alloc.cta_group::1.sync.aligned.shared::cta.b32 [%0], %1;" :: "r"(a), "r"(n) : "memory")
#define TC_RELINQ()      asm volatile("tcgen05.relinquish_alloc_permit.cta_group::1.sync.aligned;")
#define TC_DEALLOC(t, n) asm volatile("tcgen05.dealloc.cta_group::1.sync.aligned.b32 %0, %1;" :: "r"(t), "r"(n))
#define TC_COMMIT(a)     asm volatile("tcgen05.commit.cta_group::1.mbarrier::arrive::one.shared::cluster.b64 [%0];" :: "r"(a) : "memory")
#define TC_WAIT_LD()     asm volatile("tcgen05.wait::ld.sync.aligned;" ::: "memory")
#define TC_FENCE_B()     asm volatile("tcgen05.fence::before_thread_sync;" ::: "memory")
#define TC_FENCE_A()     asm volatile("tcgen05.fence::after_thread_sync;" ::: "memory")
#define FENCE_PROXY()    asm volatile("fence.proxy.async.shared::cta;" ::: "memory")

#define TC_LD_X32(r, a) \
    asm volatile("tcgen05.ld.sync.aligned.32x32b.x32.b32 " \
        "{%0,%1,%2,%3,%4,%5,%6,%7,%8,%9,%10,%11,%12,%13,%14,%15," \
        "%16,%17,%18,%19,%20,%21,%22,%23,%24,%25,%26,%27,%28,%29,%30,%31}, [%32];" \
        : "=r"((r)[0]), "=r"((r)[1]), "=r"((r)[2]), "=r"((r)[3]), \
          "=r"((r)[4]), "=r"((r)[5]), "=r"((r)[6]), "=r"((r)[7]), \
          "=r"((r)[8]), "=r"((r)[9]), "=r"((r)[10]), "=r"((r)[11]), \
          "=r"((r)[12]), "=r"((r)[13]), "=r"((r)[14]), "=r"((r)[15]), \
          "=r"((r)[16]), "=r"((r)[17]), "=r"((r)[18]), "=r"((r)[19]), \
          "=r"((r)[20]), "=r"((r)[21]), "=r"((r)[22]), "=r"((r)[23]), \
          "=r"((r)[24]), "=r"((r)[25]), "=r"((r)[26]), "=r"((r)[27]), \
          "=r"((r)[28]), "=r"((r)[29]), "=r"((r)[30]), "=r"((r)[31]) \
        : "r"(a))

__device__ __forceinline__ void mma_f16_ss(uint32_t d, uint64_t ad, uint64_t bd,
                                           uint32_t idesc, bool acc) {
    uint32_t en = acc ? 1u : 0u;
    asm volatile(
        "{ .reg .pred p; setp.ne.u32 p, %5, 0;\n\t"
        "tcgen05.mma.cta_group::1.kind::f16 [%0], %1, %2, %3, {%4,%4,%4,%4}, p; }"
        :: "r"(d), "l"(ad), "l"(bd), "r"(idesc), "r"(0u), "r"(en) : "memory");
}
__device__ __forceinline__ uint64_t mk_desc(uint32_t base) {
    const uint64_t BASE = (uint64_t(2) << 61) | (uint64_t(1) << 46) |
                          (uint64_t(64) << 32) | (uint64_t(1) << 16);
    return BASE | ((uint64_t)(base >> 4) & 0x3FFF);
}
#define SWZ(x) ((x) ^ (((x) >> 3) & 0x70))
__device__ __forceinline__ int off128(int r, int k) {
    return ((r >> 3) + (k >> 6) * 16) * 1024 + (r & 7) * 128 + (k & 63) * 2;
}
__device__ __forceinline__ int off64(int r, int k) {
    return ((r >> 3) + (k >> 6) * 8) * 1024 + (r & 7) * 128 + (k & 63) * 2;
}
#define IDESC 0x8100490u
#endif // TC_OK

#define OFF_Q  1024
#define OFF_K0 50176
#define OFF_V0 99328
#define OFF_P  132096
#define SMEM_ATTN_TC 164864
#define SMEM_ATTN_FB 69632

// mbarriers: sb+16 = QK even, sb+24 = QK odd, sb+32 = PV
// TMEM: S0 cols 0..63, S1 cols 64..127, O cols 128..191
__global__ void __launch_bounds__(256, 1) attn_tc_kernel() {
#if TC_OK
    extern __shared__ char smem[];
    uint32_t sb = smem_u32(smem);
    int tid = threadIdx.x, wid = tid >> 5, lid = tid & 31;
    int qb = blockIdx.x >> 1, half = blockIdx.x & 1;
    int n0 = qb * 128;
    int m_base = half * NT_HALF * 64;

    if (wid == 0) { TC_ALLOC(sb, 256); TC_RELINQ(); }
    if (tid == 0) {
        MBAR_INIT(sb + 16, 1); MBAR_INIT(sb + 24, 1); MBAR_INIT(sb + 32, 1);
    }

    // Prologue staging: Q, K(0), K(1), V(0)
    for (int i = tid; i < 3072; i += 256) {
        int r = i / 24, ch = i % 24;
        uint4 v = reinterpret_cast<const uint4*>(g_qs)[(n0 + r) * 24 + ch];
        *reinterpret_cast<uint4*>(smem + OFF_Q + SWZ(off128(r, ch * 8))) = v;
    }
    for (int i = tid; i < 1536; i += 256) {   // K(0) -> buf0 (FIXED: full tile)
        int r = i / 24, ch = i % 24;
        uint4 v = reinterpret_cast<const uint4*>(g_ks)[(m_base + r) * 24 + ch];
        *reinterpret_cast<uint4*>(smem + OFF_K0 + SWZ(off64(r, ch * 8))) = v;
    }
    for (int i = tid; i < 1536; i += 256) {   // K(1) -> buf1 (FIXED: full tile)
        int r = i / 24, ch = i % 24;
        uint4 v = reinterpret_cast<const uint4*>(g_ks)[(m_base + 64 + r) * 24 + ch];
        *reinterpret_cast<uint4*>(smem + OFF_K0 + 24576 + SWZ(off64(r, ch * 8))) = v;
    }
    for (int i = tid; i < 1024; i += 256) {   // V(0) -> buf0
        int r = i >> 4, ch = i & 15;
        uint4 v = reinterpret_cast<const uint4*>(g_vs)[
            (r * 2 + (ch >> 3)) * 1152 + (m_base >> 3) + (ch & 7)];
        *reinterpret_cast<uint4*>(smem + OFF_V0 + SWZ(off64(r, ch * 8))) = v;
    }
    FENCE_PROXY();
    __syncthreads();

    uint32_t tmem;
    asm volatile("ld.shared.b32 %0, [%1];" : "=r"(tmem) : "r"(sb));

    const int sa[6] = {0, 0, 1, 1, 0, 2}, sbg[6] = {0, 1, 0, 1, 2, 0};
    const int pa[3] = {0, 1, 0}, vbg[3] = {0, 0, 1};
    uint64_t qd = mk_desc(sb + OFF_Q);
    uint64_t pd = mk_desc(sb + OFF_P);

    if (wid == 0 && elect_one()) {            // QK(0) -> S0
        TC_FENCE_A();
        uint64_t kd = mk_desc(sb + OFF_K0);
        bool first = true;
#pragma unroll
        for (int g = 0; g < 6; g++)
#pragma unroll
            for (int ks = 0; ks < 4; ks++) {
                mma_f16_ss(tmem, qd + sa[g] * 1024 + ks * 2,
                           kd + sbg[g] * 512 + ks * 2, IDESC, !first);
                first = false;
            }
        TC_COMMIT(sb + 16);
    }

    int r = (wid & 3) * 32 + lid;             // my TMEM/P row
    int cb = (wid >> 2) * 32;                 // my column half: 0 or 32
    float m_n = 0.6f * g_qn[n0 + r] * __int_as_float(g_KmaxBits);
    float l_acc = 0.f;
    int ph0 = 0, ph1 = 0, ph_pv = 0;

    for (int t = 0; t < NT_HALF; t++) {
        int sbuf = t & 1;
        if (sbuf == 0) { MBAR_WAIT(sb + 16, ph0); ph0 ^= 1; }
        else           { MBAR_WAIT(sb + 24, ph1); ph1 ^= 1; }
        TC_FENCE_A();

        uint32_t sr[32];
        TC_LD_X32(sr, tmem + sbuf * 64 + cb);
        TC_WAIT_LD();
        TC_FENCE_B();

        // issue QK(t+1) into the other S buffer (K(t+1) staged last iter)
        if (t + 1 < NT_HALF && wid == 0 && elect_one()) {
            uint64_t kd = mk_desc(sb + OFF_K0 + ((t + 1) & 1) * 24576);
            uint32_t dst = tmem + ((t + 1) & 1) * 64;
            bool first = true;
#pragma unroll
            for (int g = 0; g < 6; g++)
#pragma unroll
                for (int ks = 0; ks < 4; ks++) {
                    mma_f16_ss(dst, qd + sa[g] * 1024 + ks * 2,
                               kd + sbg[g] * 512 + ks * 2, IDESC, !first);
                    first = false;
                }
            TC_COMMIT(((t + 1) & 1) ? (sb + 24) : (sb + 16));
        }

        // stage K(t+2) into buf[t&1] (QK(t) completion observed above)
        if (t + 2 < NT_HALF) {
            int m1 = m_base + (t + 2) * 64;
            uint32_t kb = OFF_K0 + sbuf * 24576;
            for (int i = tid; i < 1536; i += 256) {
                int rr = i / 24, ch = i % 24;
                uint4 v = reinterpret_cast<const uint4*>(g_ks)[(m1 + rr) * 24 + ch];
                *reinterpret_cast<uint4*>(smem + kb + SWZ(off64(rr, ch * 8))) = v;
            }
        }

        // wait PV(t-1) done: frees P and V[(t+1)&1]
        if (t > 0) { MBAR_WAIT(sb + 32, ph_pv); ph_pv ^= 1; }

        // stage V(t+1) into buf[(t+1)&1]
        if (t + 1 < NT_HALF) {
            int m1 = m_base + (t + 1) * 64;
            uint32_t vb = OFF_V0 + ((t + 1) & 1) * 16384;
            for (int i = tid; i < 1024; i += 256) {
                int rr = i >> 4, ch = i & 15;
                uint4 v = reinterpret_cast<const uint4*>(g_vs)[
                    (rr * 2 + (ch >> 3)) * 1152 + (m1 >> 3) + (ch & 7)];
                *reinterpret_cast<uint4*>(smem + vb + SWZ(off64(rr, ch * 8))) = v;
            }
        }

        // softmax epilogue: 32 elements (cols cb..cb+31 of row r)
#pragma unroll
        for (int ch = 0; ch < 4; ch++) {
            uint32_t w0[4], w1[4];
#pragma unroll
            for (int q = 0; q < 4; q++) {
                uint32_t lo0 = 0, lo1 = 0;
#pragma unroll
                for (int e = 0; e < 2; e++) {
                    float s = __uint_as_float(sr[ch * 8 + q * 2 + e]);
                    s = (fabsf(s) > 0.3f) ? s : 0.f;
                    float p = __expf(s - m_n);
                    l_acc += p;
                    __nv_bfloat16 h0 = __float2bfloat16(p);
                    __nv_bfloat16 h1 = __float2bfloat16(p - __bfloat162float(h0));
                    lo0 |= (uint32_t)__bfloat16_as_ushort(h0) << (16 * e);
                    lo1 |= (uint32_t)__bfloat16_as_ushort(h1) << (16 * e);
                }
                w0[q] = lo0; w1[q] = lo1;
            }
            *reinterpret_cast<uint4*>(smem + OFF_P + SWZ(off128(r, cb + ch * 8))) =
                make_uint4(w0[0], w0[1], w0[2], w0[3]);
            *reinterpret_cast<uint4*>(smem + OFF_P + SWZ(off128(r, 64 + cb + ch * 8))) =
                make_uint4(w1[0], w1[1], w1[2], w1[3]);
        }
        FENCE_PROXY();
        __syncthreads();   // P(t), K(t+2), V(t+1) visible to all

        if (wid == 0 && elect_one()) {        // PV(t) -> O (cols 128..191)
            uint64_t vd = mk_desc(sb + OFF_V0 + sbuf * 16384);
#pragma unroll
            for (int g = 0; g < 3; g++)
#pragma unroll
                for (int ks = 0; ks < 4; ks++) {
                    bool acc = !(t == 0 && g == 0 && ks == 0);
                    mma_f16_ss(tmem + 128, pd + pa[g] * 1024 + ks * 2,
                               vd + vbg[g] * 512 + ks * 2, IDESC, acc);
                }
            TC_COMMIT(sb + 32);
        }
    }

    // Final: read O half, combine l across column-half warps
    MBAR_WAIT(sb + 32, ph_pv);
    TC_FENCE_A();
    uint32_t orr[32];
    TC_LD_X32(orr, tmem + 128 + cb);
    TC_WAIT_LD();
    TC_FENCE_B();

    float* lsm = reinterpret_cast<float*>(smem + OFF_Q);   // Q is dead now
    lsm[tid] = l_acc;
    __syncthreads();

    int n = n0 + r;
#pragma unroll
    for (int j = 0; j < 32; j++)
        g_O[(half * 64 + cb + j) * N_PIX + n] = __uint_as_float(orr[j]);
    if (wid < 4)
        g_l[half * N_PIX + n] = lsm[tid] + lsm[tid + 128];

    __syncthreads();
    if (wid == 0) TC_DEALLOC(tmem, 256);
#endif
}

__global__ void merge_kernel(const float* __restrict__ x, float* __restrict__ out) {
#if TC_OK
    int i = blockIdx.x * 256 + threadIdx.x;      // i = c*9216 + n
    int n = i % N_PIX;
    float l = g_l[n] + g_l[N_PIX + n];
    float o = g_O[i] + g_O[64 * N_PIX + i];
    out[i] = x[i] + o / l;
#endif
}

// ============================ fp32 fallback path =============================
__global__ void __launch_bounds__(256, 1)
attn_fb_kernel(const float* __restrict__ x, float* __restrict__ out) {
#if !TC_OK
    extern __shared__ float fsm[];
    float* Qs = fsm;
    float* Ks = Qs + 64 * 68;
    float* Ps = Ks + 64 * 68;
    float* Vs = Ps + 64 * 68;

    int tid = threadIdx.x;
    int tx = tid % 16, ty = tid / 16;
    int n0 = blockIdx.x * 64;

    for (int i = tid; i < 64 * 16; i += 256) {
        int n  = i / 16;
        int cq = (i % 16) * 4;
        float4 q = *reinterpret_cast<const float4*>(&g_y[(n0 + n) * 64 + cq]);
        Qs[(cq + 0) * 68 + n] = q.x;
        Qs[(cq + 1) * 68 + n] = q.y;
        Qs[(cq + 2) * 68 + n] = q.z;
        Qs[(cq + 3) * 68 + n] = q.w;
    }

    float O[4][4];
    float mrow[4], lrow[4];
#pragma unroll
    for (int i = 0; i < 4; i++) {
        mrow[i] = -1e30f; lrow[i] = 0.f;
#pragma unroll
        for (int j = 0; j < 4; j++) O[i][j] = 0.f;
    }
    __syncthreads();

    for (int t = 0; t < 144; t++) {
        int m0 = t * 64;
        for (int i = tid; i < 64 * 16; i += 256) {
            int row = i / 16;
            int q4  = (i % 16) * 4;
            float4 kv = *reinterpret_cast<const float4*>(&g_y[row * N_PIX + m0 + q4]);
            *reinterpret_cast<float4*>(&Ks[row * 68 + q4]) = kv;
            float4 vv = *reinterpret_cast<const float4*>(&g_v[(m0 + row) * 64 + q4]);
            *reinterpret_cast<float4*>(&Vs[row * 68 + q4]) = vv;
        }
        __syncthreads();

        float s[4][4];
#pragma unroll
        for (int i = 0; i < 4; i++)
#pragma unroll
            for (int j = 0; j < 4; j++) s[i][j] = 0.f;
#pragma unroll 8
        for (int c = 0; c < 64; c++) {
            float4 qv = *reinterpret_cast<const float4*>(&Qs[c * 68 + ty * 4]);
            float4 kv = *reinterpret_cast<const float4*>(&Ks[c * 68 + tx * 4]);
            float qa[4] = {qv.x, qv.y, qv.z, qv.w};
            float ka[4] = {kv.x, kv.y, kv.z, kv.w};
#pragma unroll
            for (int i = 0; i < 4; i++)
#pragma unroll
                for (int j = 0; j < 4; j++)
                    s[i][j] += qa[i] * ka[j];
        }

        float tmax[4];
#pragma unroll
        for (int i = 0; i < 4; i++) {
            float mx = -1e30f;
#pragma unroll
            for (int j = 0; j < 4; j++) {
                float v = s[i][j];
                v = (fabsf(v) > 0.3f) ? v : 0.f;
                s[i][j] = v;
                mx = fmaxf(mx, v);
            }
            tmax[i] = mx;
        }
#pragma unroll
        for (int off = 8; off >= 1; off >>= 1)
#pragma unroll
            for (int i = 0; i < 4; i++)
                tmax[i] = fmaxf(tmax[i], __shfl_xor_sync(0xffffffffu, tmax[i], off, 16));

        float tsum[4];
#pragma unroll
        for (int i = 0; i < 4; i++) {
            float newm = fmaxf(mrow[i], tmax[i]);
            float corr = __expf(mrow[i] - newm);
            mrow[i] = newm;
            float sum = 0.f;
#pragma unroll
            for (int j = 0; j < 4; j++) {
                float p = __expf(s[i][j] - newm);
                s[i][j] = p;
                sum += p;
            }
            tsum[i] = sum;
            lrow[i] *= corr;
#pragma unroll
            for (int j = 0; j < 4; j++) O[i][j] *= corr;
        }
#pragma unroll
        for (int off = 8; off >= 1; off >>= 1)
#pragma unroll
            for (int i = 0; i < 4; i++)
                tsum[i] += __shfl_xor_sync(0xffffffffu, tsum[i], off, 16);
#pragma unroll
        for (int i = 0; i < 4; i++) lrow[i] += tsum[i];

#pragma unroll
        for (int i = 0; i < 4; i++)
            *reinterpret_cast<float4*>(&Ps[(ty * 4 + i) * 68 + tx * 4]) =
                make_float4(s[i][0], s[i][1], s[i][2], s[i][3]);
        __syncthreads();

#pragma unroll 2
        for (int m = 0; m < 64; m += 4) {
            float4 pv[4], vv[4];
#pragma unroll
            for (int i = 0; i < 4; i++)
                pv[i] = *reinterpret_cast<const float4*>(&Ps[(ty * 4 + i) * 68 + m]);
#pragma unroll
            for (int rr = 0; rr < 4; rr++)
                vv[rr] = *reinterpret_cast<const float4*>(&Vs[(m + rr) * 68 + tx * 4]);
#pragma unroll
            for (int i = 0; i < 4; i++) {
                float pa[4] = {pv[i].x, pv[i].y, pv[i].z, pv[i].w};
#pragma unroll
                for (int rr = 0; rr < 4; rr++) {
                    O[i][0] += pa[rr] * vv[rr].x;
                    O[i][1] += pa[rr] * vv[rr].y;
                    O[i][2] += pa[rr] * vv[rr].z;
                    O[i][3] += pa[rr] * vv[rr].w;
                }
            }
        }
        __syncthreads();
    }

#pragma unroll
    for (int i = 0; i < 4; i++) {
        float inv = 1.f / lrow[i];
        int n = n0 + ty * 4 + i;
#pragma unroll
        for (int j = 0; j < 4; j++) {
            int c = tx * 4 + j;
            int idx = c * N_PIX + n;
            out[idx] = x[idx] + O[i][j] * inv;
        }
    }
#endif
}

// ---------------------------------------------------------------------------
extern "C" void kernel_launch(void* const* d_in, const int* in_sizes, int n_in,
                              void* d_out, int out_size) {
    const float* x  = (const float*)d_in[0];
    const float* dW = (const float*)d_in[1];
    const float* db = (const float*)d_in[2];
    const float* cW = (const float*)d_in[3];
    const float* cb = (const float*)d_in[4];
    float* out = (float*)d_out;

    cudaFuncSetAttribute(dconv_kernel,   cudaFuncAttributeMaxDynamicSharedMemorySize, 76800);
    cudaFuncSetAttribute(attn_tc_kernel, cudaFuncAttributeMaxDynamicSharedMemorySize, SMEM_ATTN_TC);
    cudaFuncSetAttribute(attn_fb_kernel, cudaFuncAttributeMaxDynamicSharedMemorySize, SMEM_ATTN_FB);

    dconv_kernel<<<96, 512, 76800>>>(x, dW, db);
    conv1x1_kernel<<<72, 128>>>(x, cW, cb);
    split_kernel<<<144, 256>>>();
    attn_tc_kernel<<<144, 256, SMEM_ATTN_TC>>>();
    attn_fb_kernel<<<144, 256, SMEM_ATTN_FB>>>(x, out);
    merge_kernel<<<2304, 256>>>(x, out);
}

// round 15
// speedup vs baseline: 1.3188x; 1.3188x over previous
#include <cuda_runtime.h>
#include <cuda_bf16.h>
#include <math.h>
#include <stdint.h>

#define N_PIX 9216
#define C_DIM 64
#define NT_HALF 72   // 144 key-tiles of 64, split-K across 2 CTAs -> 72 each

// Does this compilation pass have the arch-specific tcgen05 ISA?
#if defined(__CUDA_ARCH_FEAT_SM103_ALL) || defined(__CUDA_ARCH_FEAT_SM100_ALL) || \
    (defined(__CUDA_ARCH_SPECIFIC__) && defined(__CUDA_ARCH__) && (__CUDA_ARCH__ == 1030))
#define TC_OK 1
#else
#define TC_OK 0
#endif

// ------------------------------ device scratch ------------------------------
__device__ float g_y[C_DIM * N_PIX];                 // dilated conv out, [c][pix]
__device__ float g_v[C_DIM * N_PIX];                 // 1x1 conv out ([m][c] flat view)
__device__ __align__(16) __nv_bfloat16 g_qs[N_PIX * 192]; // [n][s*64+c]
__device__ __align__(16) __nv_bfloat16 g_ks[N_PIX * 192]; // [m][s*64+c]
__device__ __align__(16) __nv_bfloat16 g_vs[64 * 2 * N_PIX]; // [(c*2+s)][m]
__device__ float g_qn[N_PIX];                        // ||q_n||
__device__ int   g_KmaxBits;                         // max_m ||k_m|| (float bits)
__device__ float g_O[2 * 64 * N_PIX];                // partial O: [(half*64+c)][n]
__device__ float g_l[2 * N_PIX];                     // partial l

// ---------------------------------------------------------------------------
// Dilated 3x3 conv
// ---------------------------------------------------------------------------
__global__ void __launch_bounds__(512, 1)
dconv_kernel(const float* __restrict__ x, const float* __restrict__ dW,
             const float* __restrict__ db) {
    extern __shared__ float xs[];
    const int ROWW = 100;
    int h = blockIdx.x, tid = threadIdx.x;
    for (int i = tid; i < 3 * 64 * ROWW; i += 512) xs[i] = 0.f;
    __syncthreads();
    for (int i = tid; i < 3 * 64 * 96; i += 512) {
        int r = i / (64 * 96), rem = i % (64 * 96);
        int ci = rem / 96, w = rem % 96;
        int hh = h + 2 * (r - 1);
        if (hh >= 0 && hh < 96)
            xs[(r * 64 + ci) * ROWW + w + 2] = x[ci * N_PIX + hh * 96 + w];
    }
    __syncthreads();
    int c = tid >> 3, w0 = (tid & 7) * 12;
    float acc[12];
    float b = __ldg(&db[c]);
#pragma unroll
    for (int k = 0; k < 12; k++) acc[k] = b;
    const float* wbase = &dW[c * 576];
    float wg[9];
#pragma unroll
    for (int t = 0; t < 9; t++) wg[t] = __ldg(&wbase[t]);
    for (int ci = 0; ci < 64; ci++) {
        float wgn[9];
        if (ci < 63) {
#pragma unroll
            for (int t = 0; t < 9; t++) wgn[t] = __ldg(&wbase[(ci + 1) * 9 + t]);
        }
#pragma unroll
        for (int r = 0; r < 3; r++) {
            const float* xp = &xs[(r * 64 + ci) * ROWW + w0];
#pragma unroll
            for (int kw = 0; kw < 3; kw++) {
                float w = wg[r * 3 + kw];
#pragma unroll
                for (int k = 0; k < 12; k++) acc[k] += xp[k + 2 * kw] * w;
            }
        }
#pragma unroll
        for (int t = 0; t < 9; t++) wg[t] = wgn[t];
    }
    float* yo = &g_y[c * N_PIX + h * 96 + w0];
#pragma unroll
    for (int k = 0; k < 12; k++) yo[k] = acc[k];
}

// ---------------------------------------------------------------------------
__global__ void conv1x1_kernel(const float* __restrict__ x,
                               const float* __restrict__ cW,
                               const float* __restrict__ cb) {
    __shared__ float ws[64 * 64];
    int tid = threadIdx.x;
    if (blockIdx.x == 0 && tid == 0) g_KmaxBits = 0;
    for (int i = tid; i < 4096; i += 128) ws[i] = cW[i];
    __syncthreads();
    int p = blockIdx.x * 128 + tid;
#pragma unroll 1
    for (int chunk = 0; chunk < 4; chunk++) {
        float acc[16];
#pragma unroll
        for (int j = 0; j < 16; j++) acc[j] = __ldg(&cb[chunk * 16 + j]);
        for (int ci = 0; ci < 64; ci++) {
            float xv = x[ci * N_PIX + p];
#pragma unroll
            for (int j = 0; j < 16; j++)
                acc[j] += xv * ws[(chunk * 16 + j) * 64 + ci];
        }
#pragma unroll
        for (int j = 0; j < 16; j++) g_v[(chunk * 16 + j) * N_PIX + p] = acc[j];
    }
}

// ---------------------------------------------------------------------------
// Split kernel: bf16 3-way splits of Q rows / K cols, 2-way split of V rows,
// plus ||q_n|| and global max ||k_m||.
// ---------------------------------------------------------------------------
__global__ void __launch_bounds__(256, 1) split_kernel() {
    __shared__ float yb[64 * 65];
    __shared__ __nv_bfloat16 ob[64 * 192];
    int tid = threadIdx.x, blk = blockIdx.x;
    int r = tid >> 2, p4 = tid & 3;

    // Q rows
    for (int i = tid; i < 4096; i += 256) yb[i] = g_y[blk * 4096 + i];
    __syncthreads();
    {
        float nrm = 0.f;
#pragma unroll
        for (int cc = 0; cc < 16; cc++) {
            int c = p4 * 16 + cc;
            float v = yb[r * 64 + c];
            nrm += v * v;
            __nv_bfloat16 b0 = __float2bfloat16(v);
            float r1 = v - __bfloat162float(b0);
            __nv_bfloat16 b1 = __float2bfloat16(r1);
            __nv_bfloat16 b2 = __float2bfloat16(r1 - __bfloat162float(b1));
            ob[r * 192 + c] = b0; ob[r * 192 + 64 + c] = b1; ob[r * 192 + 128 + c] = b2;
        }
        nrm += __shfl_xor_sync(0xffffffffu, nrm, 1);
        nrm += __shfl_xor_sync(0xffffffffu, nrm, 2);
        if (p4 == 0) g_qn[blk * 64 + r] = sqrtf(nrm);
    }
    __syncthreads();
    for (int i = tid; i < 1536; i += 256)
        reinterpret_cast<uint4*>(g_qs)[blk * 1536 + i] =
            reinterpret_cast<const uint4*>(ob)[i];
    __syncthreads();

    // K cols
    for (int i = tid; i < 4096; i += 256) {
        int c = i >> 6, ml = i & 63;
        yb[ml * 65 + c] = g_y[c * N_PIX + blk * 64 + ml];
    }
    __syncthreads();
    {
        float nrm = 0.f;
#pragma unroll
        for (int cc = 0; cc < 16; cc++) {
            int c = p4 * 16 + cc;
            float v = yb[r * 65 + c];
            nrm += v * v;
            __nv_bfloat16 b0 = __float2bfloat16(v);
            float r1 = v - __bfloat162float(b0);
            __nv_bfloat16 b1 = __float2bfloat16(r1);
            __nv_bfloat16 b2 = __float2bfloat16(r1 - __bfloat162float(b1));
            ob[r * 192 + c] = b0; ob[r * 192 + 64 + c] = b1; ob[r * 192 + 128 + c] = b2;
        }
        nrm += __shfl_xor_sync(0xffffffffu, nrm, 1);
        nrm += __shfl_xor_sync(0xffffffffu, nrm, 2);
        if (p4 == 0) atomicMax(&g_KmaxBits, __float_as_int(sqrtf(nrm)));
    }
    __syncthreads();
    for (int i = tid; i < 1536; i += 256)
        reinterpret_cast<uint4*>(g_ks)[blk * 1536 + i] =
            reinterpret_cast<const uint4*>(ob)[i];
    __syncthreads();

    // V rows, 2-way split, stored transposed [(c*2+s)][m]
    for (int i = tid; i < 4096; i += 256) yb[i] = g_v[blk * 4096 + i];
    __syncthreads();
#pragma unroll
    for (int cc = 0; cc < 16; cc++) {
        int c = p4 * 16 + cc;
        float v = yb[r * 64 + c];
        __nv_bfloat16 b0 = __float2bfloat16(v);
        __nv_bfloat16 b1 = __float2bfloat16(v - __bfloat162float(b0));
        ob[(c * 2 + 0) * 64 + r] = b0;
        ob[(c * 2 + 1) * 64 + r] = b1;
    }
    __syncthreads();
    for (int i = tid; i < 1024; i += 256)
        reinterpret_cast<uint4*>(g_vs)[(i >> 3) * 1152 + blk * 8 + (i & 7)] =
            reinterpret_cast<const uint4*>(ob)[i];
}

// ============================ tcgen05 path ===================================
#if TC_OK
__device__ __forceinline__ uint32_t smem_u32(const void* p) {
    uint32_t a;
    asm("{ .reg .u64 t; cvta.to.shared.u64 t, %1; cvt.u32.u64 %0, t; }"
        : "=r"(a) : "l"(p));
    return a;
}
__device__ __forceinline__ uint32_t elect_one() {
    uint32_t pred;
    asm volatile("{ .reg .pred p; elect.sync _|p, 0xFFFFFFFF; selp.b32 %0,1,0,p; }"
                 : "=r"(pred));
    return pred;
}
#define MBAR_INIT(a, c) \
    asm volatile("mbarrier.init.shared.b64 [%0], %1;" :: "r"(a), "r"(c) : "memory")
#define MBAR_WAIT(a, ph) do {                                                    \
    uint32_t _m = (a), _p = (uint32_t)(ph), _d;                                  \
    asm volatile("{ .reg .pred p; mbarrier.try_wait.parity.acquire.cta.shared::cta.b64 p, [%1], %2;" \
                 " selp.b32 %0,1,0,p; }" : "=r"(_d) : "r"(_m), "r"(_p) : "memory"); \
    if (!_d) asm volatile("{ .reg .pred P1; W%=:\n\t"                            \
                 "mbarrier.try_wait.parity.acquire.cta.shared::cta.b64 P1, [%0], %1, 0x989680;\n\t" \
                 "@P1 bra.uni D%=;\n\t bra.uni W%=;\n\t D%=: }"                  \
                 :: "r"(_m), "r"(_p) : "memory");                                \
} while (0)
#define TC_ALLOC(a, n)   asm volatile("tcgen05.alloc.cta_group::1.sync.aligned.shared::cta.b32 [%0], %1;" :: "r"(a), "r"(n) : "memory")
#define TC_RELINQ()      asm volatile("tcgen05.relinquish_alloc_permit.cta_group::1.sync.aligned;")
#define TC_DEALLOC(t, n) asm volatile("tcgen05.dealloc.cta_group::1.sync.aligned.b32 %0, %1;" :: "r"(t), "r"(n))
#define TC_COMMIT(a)     asm volatile("tcgen05.commit.cta_group::1.mbarrier::arrive::one.shared::cluster.b64 [%0];" :: "r"(a) : "memory")
#define TC_WAIT_LD()     asm volatile("tcgen05.wait::ld.sync.aligned;" ::: "memory")
#define TC_FENCE_B()     asm volatile("tcgen05.fence::before_thread_sync;" ::: "memory")
#define TC_FENCE_A()     asm volatile("tcgen05.fence::after_thread_sync;" ::: "memory")
#define FENCE_PROXY()    asm volatile("fence.proxy.async.shared::cta;" ::: "memory")
#define PROD_BAR()       asm volatile("bar.sync 1, 128;" ::: "memory")

#define TC_LD_X32(r, a) \
    asm volatile("tcgen05.ld.sync.aligned.32x32b.x32.b32 " \
        "{%0,%1,%2,%3,%4,%5,%6,%7,%8,%9,%10,%11,%12,%13,%14,%15," \
        "%16,%17,%18,%19,%20,%21,%22,%23,%24,%25,%26,%27,%28,%29,%30,%31}, [%32];" \
        : "=r"((r)[0]), "=r"((r)[1]), "=r"((r)[2]), "=r"((r)[3]), \
          "=r"((r)[4]), "=r"((r)[5]), "=r"((r)[6]), "=r"((r)[7]), \
          "=r"((r)[8]), "=r"((r)[9]), "=r"((r)[10]), "=r"((r)[11]), \
          "=r"((r)[12]), "=r"((r)[13]), "=r"((r)[14]), "=r"((r)[15]), \
          "=r"((r)[16]), "=r"((r)[17]), "=r"((r)[18]), "=r"((r)[19]), \
          "=r"((r)[20]), "=r"((r)[21]), "=r"((r)[22]), "=r"((r)[23]), \
          "=r"((r)[24]), "=r"((r)[25]), "=r"((r)[26]), "=r"((r)[27]), \
          "=r"((r)[28]), "=r"((r)[29]), "=r"((r)[30]), "=r"((r)[31]) \
        : "r"(a))

__device__ __forceinline__ void mma_f16_ss(uint32_t d, uint64_t ad, uint64_t bd,
                                           uint32_t idesc, bool acc) {
    uint32_t en = acc ? 1u : 0u;
    asm volatile(
        "{ .reg .pred p; setp.ne.u32 p, %5, 0;\n\t"
        "tcgen05.mma.cta_group::1.kind::f16 [%0], %1, %2, %3, {%4,%4,%4,%4}, p; }"
        :: "r"(d), "l"(ad), "l"(bd), "r"(idesc), "r"(0u), "r"(en) : "memory");
}
__device__ __forceinline__ uint64_t mk_desc(uint32_t base) {
    const uint64_t BASE = (uint64_t(2) << 61) | (uint64_t(1) << 46) |
                          (uint64_t(64) << 32) | (uint64_t(1) << 16);
    return BASE | ((uint64_t)(base >> 4) & 0x3FFF);
}
#define SWZ(x) ((x) ^ (((x) >> 3) & 0x70))
__device__ __forceinline__ int off128(int r, int k) {
    return ((r >> 3) + (k >> 6) * 16) * 1024 + (r & 7) * 128 + (k & 63) * 2;
}
__device__ __forceinline__ int off64(int r, int k) {
    return ((r >> 3) + (k >> 6) * 8) * 1024 + (r & 7) * 128 + (k & 63) * 2;
}
#define IDESC 0x8100490u
#endif // TC_OK

#define OFF_Q  1024
#define OFF_K0 50176
#define OFF_V0 99328
#define OFF_P  132096
#define SMEM_ATTN_TC 164864
#define SMEM_ATTN_FB 69632

// 384 threads: warps 0-7 consumers (row x col-half), warps 8-11 producers.
// mbarriers: sb+16 = QK even, sb+24 = QK odd, sb+32 = PV
// TMEM: S0 cols 0..63, S1 cols 64..127, O cols 128..191
__global__ void __launch_bounds__(384, 1) attn_tc_kernel() {
#if TC_OK
    extern __shared__ char smem[];
    uint32_t sb = smem_u32(smem);
    int tid = threadIdx.x, wid = tid >> 5, lid = tid & 31;
    int qb = blockIdx.x >> 1, half = blockIdx.x & 1;
    int n0 = qb * 128;
    int m_base = half * NT_HALF * 64;

    if (wid == 8) { TC_ALLOC(sb, 256); TC_RELINQ(); }
    if (tid == 0) {
        MBAR_INIT(sb + 16, 1); MBAR_INIT(sb + 24, 1); MBAR_INIT(sb + 32, 1);
    }

    // Prologue staging (all 384): Q, K(0), K(1), V(0)
    for (int i = tid; i < 3072; i += 384) {
        int r = i / 24, ch = i % 24;
        uint4 v = reinterpret_cast<const uint4*>(g_qs)[(n0 + r) * 24 + ch];
        *reinterpret_cast<uint4*>(smem + OFF_Q + SWZ(off128(r, ch * 8))) = v;
    }
    for (int i = tid; i < 1536; i += 384) {   // K(0) -> buf0
        int r = i / 24, ch = i % 24;
        uint4 v = reinterpret_cast<const uint4*>(g_ks)[(m_base + r) * 24 + ch];
        *reinterpret_cast<uint4*>(smem + OFF_K0 + SWZ(off64(r, ch * 8))) = v;
    }
    for (int i = tid; i < 1536; i += 384) {   // K(1) -> buf1
        int r = i / 24, ch = i % 24;
        uint4 v = reinterpret_cast<const uint4*>(g_ks)[(m_base + 64 + r) * 24 + ch];
        *reinterpret_cast<uint4*>(smem + OFF_K0 + 24576 + SWZ(off64(r, ch * 8))) = v;
    }
    for (int i = tid; i < 1024; i += 384) {   // V(0) -> buf0
        int r = i >> 4, ch = i & 15;
        uint4 v = reinterpret_cast<const uint4*>(g_vs)[
            (r * 2 + (ch >> 3)) * 1152 + (m_base >> 3) + (ch & 7)];
        *reinterpret_cast<uint4*>(smem + OFF_V0 + SWZ(off64(r, ch * 8))) = v;
    }
    FENCE_PROXY();
    __syncthreads();

    uint32_t tmem;
    asm volatile("ld.shared.b32 %0, [%1];" : "=r"(tmem) : "r"(sb));

    const int sa[6] = {0, 0, 1, 1, 0, 2}, sbg[6] = {0, 1, 0, 1, 2, 0};
    const int pa[3] = {0, 1, 0}, vbg[3] = {0, 0, 1};
    uint64_t qd = mk_desc(sb + OFF_Q);
    uint64_t pd = mk_desc(sb + OFF_P);

    if (wid == 8 && elect_one()) {            // QK(0) -> S0
        TC_FENCE_A();
        uint64_t kd = mk_desc(sb + OFF_K0);
        bool first = true;
#pragma unroll
        for (int g = 0; g < 6; g++)
#pragma unroll
            for (int ks = 0; ks < 4; ks++) {
                mma_f16_ss(tmem, qd + sa[g] * 1024 + ks * 2,
                           kd + sbg[g] * 512 + ks * 2, IDESC, !first);
                first = false;
            }
        TC_COMMIT(sb + 16);
    }

    int r = (wid & 3) * 32 + lid;             // consumer row (wid<8)
    int cb = ((wid >> 2) & 1) * 32;           // consumer column half
    float m_n = 0.f, l_acc = 0.f;
    if (wid < 8)
        m_n = 0.6f * g_qn[n0 + r] * __int_as_float(g_KmaxBits);
    int ph0 = 0, ph1 = 0, ph_pv = 0;
    int ptid = tid - 256;                     // producer-local tid (warps 8-11)

    for (int t = 0; t < NT_HALF; t++) {
        int sbuf = t & 1;
        if (wid >= 8) {
            // ---- producers: stage K(t+1), then issue QK(t+1) ----
            if (t + 1 < NT_HALF) {
                int m1 = m_base + (t + 1) * 64;
                uint32_t kb = OFF_K0 + ((t + 1) & 1) * 24576;
                for (int i = ptid; i < 1536; i += 128) {
                    int rr = i / 24, ch = i % 24;
                    uint4 v = reinterpret_cast<const uint4*>(g_ks)[(m1 + rr) * 24 + ch];
                    *reinterpret_cast<uint4*>(smem + kb + SWZ(off64(rr, ch * 8))) = v;
                }
                FENCE_PROXY();
            }
            PROD_BAR();
            if (t + 1 < NT_HALF && wid == 8 && elect_one()) {
                TC_FENCE_A();
                uint64_t kd = mk_desc(sb + OFF_K0 + ((t + 1) & 1) * 24576);
                uint32_t dst = tmem + ((t + 1) & 1) * 64;
                bool first = true;
#pragma unroll
                for (int g = 0; g < 6; g++)
#pragma unroll
                    for (int ks = 0; ks < 4; ks++) {
                        mma_f16_ss(dst, qd + sa[g] * 1024 + ks * 2,
                                   kd + sbg[g] * 512 + ks * 2, IDESC, !first);
                        first = false;
                    }
                TC_COMMIT(((t + 1) & 1) ? (sb + 24) : (sb + 16));
            }
        } else {
            // ---- consumers: softmax epilogue, 32 cols of row r ----
            if (sbuf == 0) { MBAR_WAIT(sb + 16, ph0); ph0 ^= 1; }
            else           { MBAR_WAIT(sb + 24, ph1); ph1 ^= 1; }
            TC_FENCE_A();
            uint32_t sr[32];
            TC_LD_X32(sr, tmem + sbuf * 64 + cb);
            TC_WAIT_LD();
            TC_FENCE_B();
            if (t > 0) { MBAR_WAIT(sb + 32, ph_pv); ph_pv ^= 1; }   // P free
#pragma unroll
            for (int ch = 0; ch < 4; ch++) {
                uint32_t w0[4], w1[4];
#pragma unroll
                for (int q = 0; q < 4; q++) {
                    uint32_t lo0 = 0, lo1 = 0;
#pragma unroll
                    for (int e = 0; e < 2; e++) {
                        float s = __uint_as_float(sr[ch * 8 + q * 2 + e]);
                        s = (fabsf(s) > 0.3f) ? s : 0.f;
                        float p = __expf(s - m_n);
                        l_acc += p;
                        __nv_bfloat16 h0 = __float2bfloat16(p);
                        __nv_bfloat16 h1 = __float2bfloat16(p - __bfloat162float(h0));
                        lo0 |= (uint32_t)__bfloat16_as_ushort(h0) << (16 * e);
                        lo1 |= (uint32_t)__bfloat16_as_ushort(h1) << (16 * e);
                    }
                    w0[q] = lo0; w1[q] = lo1;
                }
                *reinterpret_cast<uint4*>(smem + OFF_P + SWZ(off128(r, cb + ch * 8))) =
                    make_uint4(w0[0], w0[1], w0[2], w0[3]);
                *reinterpret_cast<uint4*>(smem + OFF_P + SWZ(off128(r, 64 + cb + ch * 8))) =
                    make_uint4(w1[0], w1[1], w1[2], w1[3]);
            }
            FENCE_PROXY();
        }
        __syncthreads();   // P(t) visible; PV(t-1)/QK(t) completion conveyed

        if (wid == 8 && elect_one()) {        // PV(t) -> O (cols 128..191)
            uint64_t vd = mk_desc(sb + OFF_V0 + sbuf * 16384);
#pragma unroll
            for (int g = 0; g < 3; g++)
#pragma unroll
                for (int ks = 0; ks < 4; ks++) {
                    bool acc = !(t == 0 && g == 0 && ks == 0);
                    mma_f16_ss(tmem + 128, pd + pa[g] * 1024 + ks * 2,
                               vd + vbg[g] * 512 + ks * 2, IDESC, acc);
                }
            TC_COMMIT(sb + 32);
        }
        // stage V(t+1) (PV(t-1) completion observed by consumers pre-bar)
        if (wid >= 8 && t + 1 < NT_HALF) {
            int m1 = m_base + (t + 1) * 64;
            uint32_t vb = OFF_V0 + ((t + 1) & 1) * 16384;
            for (int i = ptid; i < 1024; i += 128) {
                int rr = i >> 4, ch = i & 15;
                uint4 v = reinterpret_cast<const uint4*>(g_vs)[
                    (rr * 2 + (ch >> 3)) * 1152 + (m1 >> 3) + (ch & 7)];
                *reinterpret_cast<uint4*>(smem + vb + SWZ(off64(rr, ch * 8))) = v;
            }
            FENCE_PROXY();
        }
    }

    // Final: consumers read O halves, combine l across column-half warps
    if (wid < 8) {
        MBAR_WAIT(sb + 32, ph_pv);            // PV(NT-1) done
        TC_FENCE_A();
        uint32_t orr[32];
        TC_LD_X32(orr, tmem + 128 + cb);
        TC_WAIT_LD();
        TC_FENCE_B();

        float* lsm = reinterpret_cast<float*>(smem + OFF_Q);   // Q dead now
        lsm[tid] = l_acc;
        __syncthreads();                      // consumers + producers both arrive

        int n = n0 + r;
#pragma unroll
        for (int j = 0; j < 32; j++)
            g_O[(half * 64 + cb + j) * N_PIX + n] = __uint_as_float(orr[j]);
        if (wid < 4)
            g_l[half * N_PIX + n] = lsm[tid] + lsm[tid + 128];
    } else {
        __syncthreads();
    }
    __syncthreads();
    if (wid == 8) TC_DEALLOC(tmem, 256);
#endif
}

__global__ void merge_kernel(const float* __restrict__ x, float* __restrict__ out) {
#if TC_OK
    int i = blockIdx.x * 256 + threadIdx.x;      // i = c*9216 + n
    int n = i % N_PIX;
    float l = g_l[n] + g_l[N_PIX + n];
    float o = g_O[i] + g_O[64 * N_PIX + i];
    out[i] = x[i] + o / l;
#endif
}

// ============================ fp32 fallback path =============================
__global__ void __launch_bounds__(256, 1)
attn_fb_kernel(const float* __restrict__ x, float* __restrict__ out) {
#if !TC_OK
    extern __shared__ float fsm[];
    float* Qs = fsm;
    float* Ks = Qs + 64 * 68;
    float* Ps = Ks + 64 * 68;
    float* Vs = Ps + 64 * 68;

    int tid = threadIdx.x;
    int tx = tid % 16, ty = tid / 16;
    int n0 = blockIdx.x * 64;

    for (int i = tid; i < 64 * 16; i += 256) {
        int n  = i / 16;
        int cq = (i % 16) * 4;
        float4 q = *reinterpret_cast<const float4*>(&g_y[(n0 + n) * 64 + cq]);
        Qs[(cq + 0) * 68 + n] = q.x;
        Qs[(cq + 1) * 68 + n] = q.y;
        Qs[(cq + 2) * 68 + n] = q.z;
        Qs[(cq + 3) * 68 + n] = q.w;
    }

    float O[4][4];
    float mrow[4], lrow[4];
#pragma unroll
    for (int i = 0; i < 4; i++) {
        mrow[i] = -1e30f; lrow[i] = 0.f;
#pragma unroll
        for (int j = 0; j < 4; j++) O[i][j] = 0.f;
    }
    __syncthreads();

    for (int t = 0; t < 144; t++) {
        int m0 = t * 64;
        for (int i = tid; i < 64 * 16; i += 256) {
            int row = i / 16;
            int q4  = (i % 16) * 4;
            float4 kv = *reinterpret_cast<const float4*>(&g_y[row * N_PIX + m0 + q4]);
            *reinterpret_cast<float4*>(&Ks[row * 68 + q4]) = kv;
            float4 vv = *reinterpret_cast<const float4*>(&g_v[(m0 + row) * 64 + q4]);
            *reinterpret_cast<float4*>(&Vs[row * 68 + q4]) = vv;
        }
        __syncthreads();

        float s[4][4];
#pragma unroll
        for (int i = 0; i < 4; i++)
#pragma unroll
            for (int j = 0; j < 4; j++) s[i][j] = 0.f;
#pragma unroll 8
        for (int c = 0; c < 64; c++) {
            float4 qv = *reinterpret_cast<const float4*>(&Qs[c * 68 + ty * 4]);
            float4 kv = *reinterpret_cast<const float4*>(&Ks[c * 68 + tx * 4]);
            float qa[4] = {qv.x, qv.y, qv.z, qv.w};
            float ka[4] = {kv.x, kv.y, kv.z, kv.w};
#pragma unroll
            for (int i = 0; i < 4; i++)
#pragma unroll
                for (int j = 0; j < 4; j++)
                    s[i][j] += qa[i] * ka[j];
        }

        float tmax[4];
#pragma unroll
        for (int i = 0; i < 4; i++) {
            float mx = -1e30f;
#pragma unroll
            for (int j = 0; j < 4; j++) {
                float v = s[i][j];
                v = (fabsf(v) > 0.3f) ? v : 0.f;
                s[i][j] = v;
                mx = fmaxf(mx, v);
            }
            tmax[i] = mx;
        }
#pragma unroll
        for (int off = 8; off >= 1; off >>= 1)
#pragma unroll
            for (int i = 0; i < 4; i++)
                tmax[i] = fmaxf(tmax[i], __shfl_xor_sync(0xffffffffu, tmax[i], off, 16));

        float tsum[4];
#pragma unroll
        for (int i = 0; i < 4; i++) {
            float newm = fmaxf(mrow[i], tmax[i]);
            float corr = __expf(mrow[i] - newm);
            mrow[i] = newm;
            float sum = 0.f;
#pragma unroll
            for (int j = 0; j < 4; j++) {
                float p = __expf(s[i][j] - newm);
                s[i][j] = p;
                sum += p;
            }
            tsum[i] = sum;
            lrow[i] *= corr;
#pragma unroll
            for (int j = 0; j < 4; j++) O[i][j] *= corr;
        }
#pragma unroll
        for (int off = 8; off >= 1; off >>= 1)
#pragma unroll
            for (int i = 0; i < 4; i++)
                tsum[i] += __shfl_xor_sync(0xffffffffu, tsum[i], off, 16);
#pragma unroll
        for (int i = 0; i < 4; i++) lrow[i] += tsum[i];

#pragma unroll
        for (int i = 0; i < 4; i++)
            *reinterpret_cast<float4*>(&Ps[(ty * 4 + i) * 68 + tx * 4]) =
                make_float4(s[i][0], s[i][1], s[i][2], s[i][3]);
        __syncthreads();

#pragma unroll 2
        for (int m = 0; m < 64; m += 4) {
            float4 pv[4], vv[4];
#pragma unroll
            for (int i = 0; i < 4; i++)
                pv[i] = *reinterpret_cast<const float4*>(&Ps[(ty * 4 + i) * 68 + m]);
#pragma unroll
            for (int rr = 0; rr < 4; rr++)
                vv[rr] = *reinterpret_cast<const float4*>(&Vs[(m + rr) * 68 + tx * 4]);
#pragma unroll
            for (int i = 0; i < 4; i++) {
                float pa[4] = {pv[i].x, pv[i].y, pv[i].z, pv[i].w};
#pragma unroll
                for (int rr = 0; rr < 4; rr++) {
                    O[i][0] += pa[rr] * vv[rr].x;
                    O[i][1] += pa[rr] * vv[rr].y;
                    O[i][2] += pa[rr] * vv[rr].z;
                    O[i][3] += pa[rr] * vv[rr].w;
                }
            }
        }
        __syncthreads();
    }

#pragma unroll
    for (int i = 0; i < 4; i++) {
        float inv = 1.f / lrow[i];
        int n = n0 + ty * 4 + i;
#pragma unroll
        for (int j = 0; j < 4; j++) {
            int c = tx * 4 + j;
            int idx = c * N_PIX + n;
            out[idx] = x[idx] + O[i][j] * inv;
        }
    }
#endif
}

// ---------------------------------------------------------------------------
extern "C" void kernel_launch(void* const* d_in, const int* in_sizes, int n_in,
                              void* d_out, int out_size) {
    const float* x  = (const float*)d_in[0];
    const float* dW = (const float*)d_in[1];
    const float* db = (const float*)d_in[2];
    const float* cW = (const float*)d_in[3];
    const float* cb = (const float*)d_in[4];
    float* out = (float*)d_out;

    cudaFuncSetAttribute(dconv_kernel,   cudaFuncAttributeMaxDynamicSharedMemorySize, 76800);
    cudaFuncSetAttribute(attn_tc_kernel, cudaFuncAttributeMaxDynamicSharedMemorySize, SMEM_ATTN_TC);
    cudaFuncSetAttribute(attn_fb_kernel, cudaFuncAttributeMaxDynamicSharedMemorySize, SMEM_ATTN_FB);

    dconv_kernel<<<96, 512, 76800>>>(x, dW, db);
    conv1x1_kernel<<<72, 128>>>(x, cW, cb);
    split_kernel<<<144, 256>>>();
    attn_tc_kernel<<<144, 384, SMEM_ATTN_TC>>>();
    attn_fb_kernel<<<144, 256, SMEM_ATTN_FB>>>(x, out);
    merge_kernel<<<2304, 256>>>(x, out);
}